// round 14
// baseline (speedup 1.0000x reference)
#include <cuda_runtime.h>
#include <cstdint>

// FCNKANLayer: out[b,o] = sum_i ( sum_h silu( B1[i,o,h] + sum_f feat[b,i,f]*W1[i,o,h,f] ) * W2[i,o,0,h] + B2[i,o,0] )
// feat = [x, sin(x), sin(2x), sin(4x), cos(x), cos(2x), cos(4x)]
// Shapes: B=256, I=128, O=128, H=32, F=7. All fp32.

#define BD    256
#define B_    256
#define I_    128
#define O_    128
#define H_    32
#define ROWS  (I_ * O_ * H_)   // 524288 (i,o,h) rows

typedef unsigned long long u64;

// Scratch (static __device__ arrays: no allocation at runtime)
__device__ u64   g_w1pk[(size_t)ROWS * 8];       // 33.5MB: per row {(w0,w0),(w1,w1),...,(w6,w6),(b1,b1)}
__device__ u64   g_w2pk[ROWS];                   // 4MB:    per row (w2,w2)
__device__ float g_partial[(size_t)I_ * O_ * B_]; // 16.7MB: partial[i][o][b]

// ---------------- packed f32x2 helpers ----------------
__device__ __forceinline__ u64 pack2(float lo, float hi) {
    u64 r; asm("mov.b64 %0,{%1,%2};" : "=l"(r) : "f"(lo), "f"(hi)); return r;
}
__device__ __forceinline__ void unpack2(u64 v, float& lo, float& hi) {
    asm("mov.b64 {%0,%1},%2;" : "=f"(lo), "=f"(hi) : "l"(v));
}
__device__ __forceinline__ u64 ffma2(u64 a, u64 b, u64 c) {
    u64 d; asm("fma.rn.f32x2 %0,%1,%2,%3;" : "=l"(d) : "l"(a), "l"(b), "l"(c)); return d;
}
__device__ __forceinline__ u64 fmul2(u64 a, u64 b) {
    u64 d; asm("mul.rn.f32x2 %0,%1,%2;" : "=l"(d) : "l"(a), "l"(b)); return d;
}
__device__ __forceinline__ float tanh_ap(float x) {
    float r; asm("tanh.approx.f32 %0,%1;" : "=f"(r) : "f"(x)); return r;
}

// silu on a packed pair: z * 0.5*(1 + tanh(z/2))
__device__ __forceinline__ u64 silu2(u64 z, u64 halfp) {
    u64 t = fmul2(z, halfp);
    float tl, th; unpack2(t, tl, th);
    u64 s = pack2(tanh_ap(tl), tanh_ap(th));
    s = ffma2(s, halfp, halfp);           // 0.5*tanh + 0.5
    return fmul2(s, z);
}

// ---------------- kernel 0: pack weights into duplicated-pair layout ----------------
__global__ void kan_prep(const float* __restrict__ W1, const float* __restrict__ W2,
                         const float* __restrict__ B1) {
    int g = blockIdx.x * blockDim.x + threadIdx.x;   // [0, ROWS*4)
    if (g >= ROWS * 4) return;
    int row = g >> 2;
    int p   = g & 3;
    const float* w = W1 + (size_t)row * 7;
    float a, b;
    if (p < 3) { a = w[2 * p]; b = w[2 * p + 1]; }
    else       { a = w[6];     b = B1[row];      }
    float4 v; v.x = a; v.y = a; v.z = b; v.w = b;
    ((float4*)g_w1pk)[g] = v;
    if (p == 0) {
        float wv = W2[row];                // W2 is [I][O][1][H] -> same flat row index
        g_w2pk[row] = pack2(wv, wv);
    }
}

// ---------------- kernel 1: fused main ----------------
// grid (4 o-tiles, 128 i), 256 threads.
// tx = tid & 63 -> 4 consecutive b (2 packed pairs); ty = tid >> 6 -> 8 o's.
// Warp-uniform (o,h) in inner loop -> conflict-free broadcast LDS.
#define SMEM_BYTES ((8192 + 1024) * 8 + 32 * 4)   // 73856

__global__ void __launch_bounds__(BD, 2) kan_main(const float* __restrict__ x,
                                                  const float* __restrict__ B2) {
    extern __shared__ u64 sm[];
    u64*   w1s = sm;                      // 32 o * 32 h * 8 u64 = 8192
    u64*   w2s = sm + 8192;               // 32 o * 32 h        = 1024
    float* b2s = (float*)(sm + 8192 + 1024);

    const int tid   = threadIdx.x;
    const int tx    = tid & 63;
    const int ty    = tid >> 6;
    const int otile = blockIdx.x;         // 0..3
    const int i     = blockIdx.y;         // 0..127

    // ---- stage weights for this (i, o-tile) into shared ----
    {
        const size_t base = ((size_t)i * O_ + (size_t)otile * 32) * H_;  // first row of tile
        const ulonglong2* s = (const ulonglong2*)(g_w1pk + base * 8);
        ulonglong2* d = (ulonglong2*)w1s;
        #pragma unroll
        for (int j = 0; j < 16; j++) d[tid + j * BD] = s[tid + j * BD];  // 4096 x 16B
        const u64* s2 = g_w2pk + base;
        #pragma unroll
        for (int j = 0; j < 4; j++) w2s[tid + j * BD] = s2[tid + j * BD];
        if (tid < 32) b2s[tid] = B2[i * O_ + otile * 32 + tid];
    }

    // ---- features for this thread's 4 b's (2 packed pairs), overlaps copy latency ----
    const int b0 = tx * 4;
    u64 fp[2][7];
    #pragma unroll
    for (int p = 0; p < 2; p++) {
        float xa = x[(size_t)(b0 + 2 * p)     * I_ + i];
        float xb = x[(size_t)(b0 + 2 * p + 1) * I_ + i];
        float sa1, ca1, sa2, ca2, sa4, ca4;
        float sb1, cb1, sb2, cb2, sb4, cb4;
        sincosf(xa,        &sa1, &ca1);
        sincosf(2.f * xa,  &sa2, &ca2);
        sincosf(4.f * xa,  &sa4, &ca4);
        sincosf(xb,        &sb1, &cb1);
        sincosf(2.f * xb,  &sb2, &cb2);
        sincosf(4.f * xb,  &sb4, &cb4);
        fp[p][0] = pack2(xa,  xb);
        fp[p][1] = pack2(sa1, sb1);
        fp[p][2] = pack2(sa2, sb2);
        fp[p][3] = pack2(sa4, sb4);
        fp[p][4] = pack2(ca1, cb1);
        fp[p][5] = pack2(ca2, cb2);
        fp[p][6] = pack2(ca4, cb4);
    }
    __syncthreads();

    const u64 halfp = pack2(0.5f, 0.5f);

    #pragma unroll 1
    for (int k = 0; k < 8; k++) {
        const int ol = ty * 8 + k;                  // local o in [0,32)
        const u64* wr  = w1s + (size_t)ol * (H_ * 8);
        const u64* w2r = w2s + (size_t)ol * H_;
        u64 acc0 = 0ull, acc1 = 0ull;

        #pragma unroll 4
        for (int h = 0; h < H_; h++) {
            const ulonglong2* r2 = (const ulonglong2*)(wr + h * 8);
            ulonglong2 qa = r2[0];                  // (w0,w0),(w1,w1)
            ulonglong2 qb = r2[1];                  // (w2,w2),(w3,w3)
            ulonglong2 qc = r2[2];                  // (w4,w4),(w5,w5)
            ulonglong2 qd = r2[3];                  // (w6,w6),(b1,b1)
            u64 w2p = w2r[h];
            {
                u64 z = ffma2(fp[0][0], qa.x, qd.y);
                z = ffma2(fp[0][1], qa.y, z);
                z = ffma2(fp[0][2], qb.x, z);
                z = ffma2(fp[0][3], qb.y, z);
                z = ffma2(fp[0][4], qc.x, z);
                z = ffma2(fp[0][5], qc.y, z);
                z = ffma2(fp[0][6], qd.x, z);
                acc0 = ffma2(silu2(z, halfp), w2p, acc0);
            }
            {
                u64 z = ffma2(fp[1][0], qa.x, qd.y);
                z = ffma2(fp[1][1], qa.y, z);
                z = ffma2(fp[1][2], qb.x, z);
                z = ffma2(fp[1][3], qb.y, z);
                z = ffma2(fp[1][4], qc.x, z);
                z = ffma2(fp[1][5], qc.y, z);
                z = ffma2(fp[1][6], qd.x, z);
                acc1 = ffma2(silu2(z, halfp), w2p, acc1);
            }
        }

        float a0, a1, a2, a3;
        unpack2(acc0, a0, a1);
        unpack2(acc1, a2, a3);
        const float b2v = b2s[ol];
        float4 v; v.x = a0 + b2v; v.y = a1 + b2v; v.z = a2 + b2v; v.w = a3 + b2v;
        const int o = otile * 32 + ol;
        *(float4*)(g_partial + ((size_t)i * O_ + o) * B_ + b0) = v;   // coalesced
    }
}

// ---------------- kernel 2: reduce over i ----------------
__global__ void kan_reduce(float* __restrict__ out) {
    int t = blockIdx.x * blockDim.x + threadIdx.x;   // [0, 32768)
    int b = t & (B_ - 1);
    int o = t >> 8;
    const float* p = g_partial + (size_t)o * B_ + b;
    float s0 = 0.f, s1 = 0.f, s2 = 0.f, s3 = 0.f;
    #pragma unroll 8
    for (int i = 0; i < I_; i += 4) {
        s0 += p[(size_t)(i + 0) * (O_ * B_)];
        s1 += p[(size_t)(i + 1) * (O_ * B_)];
        s2 += p[(size_t)(i + 2) * (O_ * B_)];
        s3 += p[(size_t)(i + 3) * (O_ * B_)];
    }
    out[(size_t)b * O_ + o] = (s0 + s1) + (s2 + s3);
}

// ---------------- launch ----------------
extern "C" void kernel_launch(void* const* d_in, const int* in_sizes, int n_in,
                              void* d_out, int out_size) {
    (void)in_sizes; (void)n_in; (void)out_size;
    const float* x  = (const float*)d_in[0];   // [256,128]
    const float* W1 = (const float*)d_in[1];   // [128,128,32,7]
    const float* W2 = (const float*)d_in[2];   // [128,128,1,32]
    const float* B1 = (const float*)d_in[3];   // [128,128,32]
    const float* B2 = (const float*)d_in[4];   // [128,128,1]
    float* out = (float*)d_out;                // [256,128]

    cudaFuncSetAttribute(kan_main, cudaFuncAttributeMaxDynamicSharedMemorySize, SMEM_BYTES);

    kan_prep<<<(ROWS * 4) / BD, BD>>>(W1, W2, B1);
    kan_main<<<dim3(4, I_), BD, SMEM_BYTES>>>(x, B2);
    kan_reduce<<<(B_ * O_) / BD, BD>>>(out);
}

// round 15
// speedup vs baseline: 1.1531x; 1.1531x over previous
#include <cuda_runtime.h>
#include <cstdint>

// FCNKANLayer: out[b,o] = sum_i ( sum_h silu( B1[i,o,h] + sum_f feat[b,i,f]*W1[i,o,h,f] ) * W2[i,o,0,h] + B2[i,o,0] )
// feat = [x, sin(x), sin(2x), sin(4x), cos(x), cos(2x), cos(4x)]
// B=256, I=128, O=128, H=32, F=7, fp32.
//
// Reformulation: stage w = 0.5*W1, b = 0.5*B1 so the dot gives y = z/2.
// silu(z)*W2 = z*sigma(z)*W2 = 2y*0.5*(1+tanh(y))*W2 = y*W2 + y*W2*tanh(y).

#define BD    256
#define B_    256
#define I_    128
#define O_    128
#define H_    32

typedef unsigned long long u64;

// Scratch: partial sums per i (deterministic two-stage reduction, no atomics)
__device__ float g_partial[(size_t)I_ * O_ * B_];   // 16.7MB  partial[i][o][b]

// ---------------- packed f32x2 helpers ----------------
__device__ __forceinline__ u64 pack2(float lo, float hi) {
    u64 r; asm("mov.b64 %0,{%1,%2};" : "=l"(r) : "f"(lo), "f"(hi)); return r;
}
__device__ __forceinline__ void unpack2(u64 v, float& lo, float& hi) {
    asm("mov.b64 {%0,%1},%2;" : "=f"(lo), "=f"(hi) : "l"(v));
}
__device__ __forceinline__ u64 ffma2(u64 a, u64 b, u64 c) {
    u64 d; asm("fma.rn.f32x2 %0,%1,%2,%3;" : "=l"(d) : "l"(a), "l"(b), "l"(c)); return d;
}
__device__ __forceinline__ u64 fmul2(u64 a, u64 b) {
    u64 d; asm("mul.rn.f32x2 %0,%1,%2;" : "=l"(d) : "l"(a), "l"(b)); return d;
}
__device__ __forceinline__ u64 fadd2(u64 a, u64 b) {
    u64 d; asm("add.rn.f32x2 %0,%1,%2;" : "=l"(d) : "l"(a), "l"(b)); return d;
}
__device__ __forceinline__ float tanh_ap(float x) {
    float r; asm("tanh.approx.f32 %0,%1;" : "=f"(r) : "f"(x)); return r;
}

// ---------------- fused main ----------------
// grid (4 o-tiles, 128 i), 256 threads, occupancy 3.
// tx = tid & 63 -> 4 consecutive b (2 packed pairs); ty = tid >> 6 -> 8 o's.
// (o,h) warp-uniform in inner loop -> conflict-free broadcast LDS.
// smem: w1s = 32o*32h rows of 8 u64 {(w0,w0)..(w6,w6),(b1,b1)} (halved),
//       w2s = 32o*32h of (w2,w2), b2s = 32 floats.
#define SMEM_BYTES ((8192 + 1024) * 8 + 32 * 4)   // 73856

__global__ void __launch_bounds__(BD, 3) kan_main(const float* __restrict__ x,
                                                  const float* __restrict__ W1,
                                                  const float* __restrict__ W2,
                                                  const float* __restrict__ B1,
                                                  const float* __restrict__ B2) {
    extern __shared__ u64 sm[];
    u64*   w1s = sm;                      // 8192 u64
    u64*   w2s = sm + 8192;               // 1024 u64
    float* b2s = (float*)(sm + 8192 + 1024);

    const int tid   = threadIdx.x;
    const int tx    = tid & 63;
    const int ty    = tid >> 6;
    const int otile = blockIdx.x;         // 0..3
    const int i     = blockIdx.y;         // 0..127

    // ---- stage + pack weights for this (i, o-tile): read W1 slice once, dup-pack halved ----
    {
        const size_t baseRow = ((size_t)i * O_ + (size_t)otile * 32) * H_;  // 1024 rows
        const float* w1g = W1 + baseRow * 7;                                 // 7168 floats, contiguous
        #pragma unroll
        for (int j = 0; j < 28; j++) {
            int f = tid + j * BD;
            int row = f / 7;
            int c   = f - row * 7;
            float v = 0.5f * __ldg(w1g + f);
            w1s[row * 8 + c] = pack2(v, v);
        }
        #pragma unroll
        for (int j = 0; j < 4; j++) {
            int r = tid + j * BD;
            float vb = 0.5f * B1[baseRow + r];
            w1s[r * 8 + 7] = pack2(vb, vb);
            float v2 = W2[baseRow + r];          // W2 [I][O][1][H] -> same flat row index
            w2s[r] = pack2(v2, v2);
        }
        if (tid < 32) b2s[tid] = B2[i * O_ + otile * 32 + tid];
    }

    // ---- features for this thread's 4 b's (2 packed pairs); fast sincos (|4x|<~25 rad) ----
    const int b0 = tx * 4;
    u64 fp[2][7];
    #pragma unroll
    for (int p = 0; p < 2; p++) {
        float xa = x[(size_t)(b0 + 2 * p)     * I_ + i];
        float xb = x[(size_t)(b0 + 2 * p + 1) * I_ + i];
        float sa1, ca1, sa2, ca2, sa4, ca4;
        float sb1, cb1, sb2, cb2, sb4, cb4;
        __sincosf(xa,       &sa1, &ca1);
        __sincosf(2.f * xa, &sa2, &ca2);
        __sincosf(4.f * xa, &sa4, &ca4);
        __sincosf(xb,       &sb1, &cb1);
        __sincosf(2.f * xb, &sb2, &cb2);
        __sincosf(4.f * xb, &sb4, &cb4);
        fp[p][0] = pack2(xa,  xb);
        fp[p][1] = pack2(sa1, sb1);
        fp[p][2] = pack2(sa2, sb2);
        fp[p][3] = pack2(sa4, sb4);
        fp[p][4] = pack2(ca1, cb1);
        fp[p][5] = pack2(ca2, cb2);
        fp[p][6] = pack2(ca4, cb4);
    }
    __syncthreads();

    #pragma unroll 1
    for (int k = 0; k < 8; k++) {
        const int ol = ty * 8 + k;                  // local o in [0,32)
        const u64* wr  = w1s + (size_t)ol * (H_ * 8);
        const u64* w2r = w2s + (size_t)ol * H_;
        u64 accT0 = 0ull, accT1 = 0ull;             // sum y*w2*tanh(y)
        u64 accL0 = 0ull, accL1 = 0ull;             // sum y*w2

        #pragma unroll 4
        for (int h = 0; h < H_; h++) {
            const ulonglong2* r2 = (const ulonglong2*)(wr + h * 8);
            ulonglong2 qa = r2[0];                  // (w0,w0),(w1,w1)
            ulonglong2 qb = r2[1];                  // (w2,w2),(w3,w3)
            ulonglong2 qc = r2[2];                  // (w4,w4),(w5,w5)
            ulonglong2 qd = r2[3];                  // (w6,w6),(b1,b1)
            u64 w2p = w2r[h];

            u64 y0 = ffma2(fp[0][0], qa.x, qd.y);
            u64 y1 = ffma2(fp[1][0], qa.x, qd.y);
            y0 = ffma2(fp[0][1], qa.y, y0);
            y1 = ffma2(fp[1][1], qa.y, y1);
            y0 = ffma2(fp[0][2], qb.x, y0);
            y1 = ffma2(fp[1][2], qb.x, y1);
            y0 = ffma2(fp[0][3], qb.y, y0);
            y1 = ffma2(fp[1][3], qb.y, y1);
            y0 = ffma2(fp[0][4], qc.x, y0);
            y1 = ffma2(fp[1][4], qc.x, y1);
            y0 = ffma2(fp[0][5], qc.y, y0);
            y1 = ffma2(fp[1][5], qc.y, y1);
            y0 = ffma2(fp[0][6], qd.x, y0);
            y1 = ffma2(fp[1][6], qd.x, y1);

            u64 zw0 = fmul2(y0, w2p);
            u64 zw1 = fmul2(y1, w2p);

            float a0, a1, c0, c1;
            unpack2(y0, a0, a1);
            unpack2(y1, c0, c1);
            u64 t0 = pack2(tanh_ap(a0), tanh_ap(a1));
            u64 t1 = pack2(tanh_ap(c0), tanh_ap(c1));

            accT0 = ffma2(zw0, t0, accT0);
            accT1 = ffma2(zw1, t1, accT1);
            accL0 = fadd2(accL0, zw0);
            accL1 = fadd2(accL1, zw1);
        }

        u64 s0 = fadd2(accT0, accL0);
        u64 s1 = fadd2(accT1, accL1);
        float a0, a1, a2, a3;
        unpack2(s0, a0, a1);
        unpack2(s1, a2, a3);
        const float b2v = b2s[ol];
        float4 v; v.x = a0 + b2v; v.y = a1 + b2v; v.z = a2 + b2v; v.w = a3 + b2v;
        const int o = otile * 32 + ol;
        *(float4*)(g_partial + ((size_t)i * O_ + o) * B_ + b0) = v;   // coalesced
    }
}

// ---------------- reduce over i ----------------
__global__ void kan_reduce(float* __restrict__ out) {
    int t = blockIdx.x * blockDim.x + threadIdx.x;   // [0, 32768)
    int b = t & (B_ - 1);
    int o = t >> 8;
    const float* p = g_partial + (size_t)o * B_ + b;
    float s0 = 0.f, s1 = 0.f, s2 = 0.f, s3 = 0.f;
    #pragma unroll 8
    for (int i = 0; i < I_; i += 4) {
        s0 += p[(size_t)(i + 0) * (O_ * B_)];
        s1 += p[(size_t)(i + 1) * (O_ * B_)];
        s2 += p[(size_t)(i + 2) * (O_ * B_)];
        s3 += p[(size_t)(i + 3) * (O_ * B_)];
    }
    out[(size_t)b * O_ + o] = (s0 + s1) + (s2 + s3);
}

// ---------------- launch ----------------
extern "C" void kernel_launch(void* const* d_in, const int* in_sizes, int n_in,
                              void* d_out, int out_size) {
    (void)in_sizes; (void)n_in; (void)out_size;
    const float* x  = (const float*)d_in[0];   // [256,128]
    const float* W1 = (const float*)d_in[1];   // [128,128,32,7]
    const float* W2 = (const float*)d_in[2];   // [128,128,1,32]
    const float* B1 = (const float*)d_in[3];   // [128,128,32]
    const float* B2 = (const float*)d_in[4];   // [128,128,1]
    float* out = (float*)d_out;                // [256,128]

    cudaFuncSetAttribute(kan_main, cudaFuncAttributeMaxDynamicSharedMemorySize, SMEM_BYTES);

    kan_main<<<dim3(4, I_), BD, SMEM_BYTES>>>(x, W1, W2, B1, B2);
    kan_reduce<<<(B_ * O_) / BD, BD>>>(out);
}

// round 16
// speedup vs baseline: 1.2553x; 1.0887x over previous
#include <cuda_runtime.h>
#include <cstdint>

// FCNKANLayer: out[b,o] = sum_i ( sum_h silu( B1[i,o,h] + sum_f feat[b,i,f]*W1[i,o,h,f] ) * W2[i,o,0,h] + B2[i,o,0] )
// feat = [x, sin(x), sin(2x), sin(4x), cos(x), cos(2x), cos(4x)]
// B=256, I=128, O=128, H=32, F=7, fp32.
//
// Reformulation: stage w = 0.5*W1, b = 0.5*B1 so the dot gives y = z/2.
// silu(z)*W2 = 2y*0.5*(1+tanh(y))*W2 = y*W2 + y*W2*tanh(y).

#define BD    256
#define B_    256
#define I_    128
#define O_    128
#define H_    32
#define NCH   8            // i-chunks for two-stage reduce
#define ICH   (I_ / NCH)   // 16

typedef unsigned long long u64;

// Scratch (static: no runtime allocation)
__device__ float g_partial[(size_t)I_ * O_ * B_];    // 16.7MB  partial[i][o][b]
__device__ float g_part2[(size_t)NCH * O_ * B_];     // 1MB     part2[c][o][b]

// ---------------- packed f32x2 helpers ----------------
__device__ __forceinline__ u64 pack2(float lo, float hi) {
    u64 r; asm("mov.b64 %0,{%1,%2};" : "=l"(r) : "f"(lo), "f"(hi)); return r;
}
__device__ __forceinline__ void unpack2(u64 v, float& lo, float& hi) {
    asm("mov.b64 {%0,%1},%2;" : "=f"(lo), "=f"(hi) : "l"(v));
}
__device__ __forceinline__ u64 ffma2(u64 a, u64 b, u64 c) {
    u64 d; asm("fma.rn.f32x2 %0,%1,%2,%3;" : "=l"(d) : "l"(a), "l"(b), "l"(c)); return d;
}
__device__ __forceinline__ u64 fmul2(u64 a, u64 b) {
    u64 d; asm("mul.rn.f32x2 %0,%1,%2;" : "=l"(d) : "l"(a), "l"(b)); return d;
}
__device__ __forceinline__ u64 fadd2(u64 a, u64 b) {
    u64 d; asm("add.rn.f32x2 %0,%1,%2;" : "=l"(d) : "l"(a), "l"(b)); return d;
}
__device__ __forceinline__ float tanh_ap(float x) {
    float r; asm("tanh.approx.f32 %0,%1;" : "=f"(r) : "f"(x)); return r;
}

// ---------------- fused main ----------------
// grid (8, 128): x = otile*2 + bhalf (bhalf fastest -> co-resident blocks share the
// same W1 slice in L2), y = i. 256 threads, occ 3.
// tx = tid & 31 -> 4 consecutive b within the half; ty = tid >> 5 -> 4 o's (k loop).
// (o,h) warp-uniform in inner loop -> conflict-free broadcast LDS.
// smem: w1s = 32o*32h rows of 8 u64 {(.5w0,.5w0)..(.5w6,.5w6),(.5b1,.5b1)},
//       w2s = 32o*32h of (w2,w2), b2s = 32 floats.  73856 bytes.
#define SMEM_BYTES ((8192 + 1024) * 8 + 32 * 4)

__global__ void __launch_bounds__(BD, 3) kan_main(const float* __restrict__ x,
                                                  const float* __restrict__ W1,
                                                  const float* __restrict__ W2,
                                                  const float* __restrict__ B1,
                                                  const float* __restrict__ B2) {
    extern __shared__ u64 sm[];
    u64*   w1s = sm;                      // 8192 u64
    u64*   w2s = sm + 8192;               // 1024 u64
    float* b2s = (float*)(sm + 8192 + 1024);

    const int tid   = threadIdx.x;
    const int tx    = tid & 31;
    const int ty    = tid >> 5;           // 0..7
    const int otile = blockIdx.x >> 1;    // 0..3
    const int bhalf = blockIdx.x & 1;     // 0..1
    const int i     = blockIdx.y;         // 0..127

    // ---- stage + pack weights for this (i, o-tile): dup-pack halved on the fly ----
    {
        const size_t baseRow = ((size_t)i * O_ + (size_t)otile * 32) * H_;  // 1024 rows
        const float* w1g = W1 + baseRow * 7;                                 // 7168 floats
        #pragma unroll
        for (int j = 0; j < 28; j++) {
            int f = tid + j * BD;
            int row = f / 7;
            int c   = f - row * 7;
            float v = 0.5f * __ldg(w1g + f);
            w1s[row * 8 + c] = pack2(v, v);
        }
        #pragma unroll
        for (int j = 0; j < 4; j++) {
            int r = tid + j * BD;
            float vb = 0.5f * B1[baseRow + r];
            w1s[r * 8 + 7] = pack2(vb, vb);
            float v2 = W2[baseRow + r];          // W2 [I][O][1][H] -> same flat row index
            w2s[r] = pack2(v2, v2);
        }
        if (tid < 32) b2s[tid] = B2[i * O_ + otile * 32 + tid];
    }

    // ---- features for this thread's 4 b's (2 packed pairs) ----
    const int b0 = bhalf * 128 + tx * 4;
    u64 fp[2][7];
    #pragma unroll
    for (int p = 0; p < 2; p++) {
        float xa = x[(size_t)(b0 + 2 * p)     * I_ + i];
        float xb = x[(size_t)(b0 + 2 * p + 1) * I_ + i];
        float sa1, ca1, sa2, ca2, sa4, ca4;
        float sb1, cb1, sb2, cb2, sb4, cb4;
        __sincosf(xa,       &sa1, &ca1);
        __sincosf(2.f * xa, &sa2, &ca2);
        __sincosf(4.f * xa, &sa4, &ca4);
        __sincosf(xb,       &sb1, &cb1);
        __sincosf(2.f * xb, &sb2, &cb2);
        __sincosf(4.f * xb, &sb4, &cb4);
        fp[p][0] = pack2(xa,  xb);
        fp[p][1] = pack2(sa1, sb1);
        fp[p][2] = pack2(sa2, sb2);
        fp[p][3] = pack2(sa4, sb4);
        fp[p][4] = pack2(ca1, cb1);
        fp[p][5] = pack2(ca2, cb2);
        fp[p][6] = pack2(ca4, cb4);
    }
    __syncthreads();

    #pragma unroll 1
    for (int k = 0; k < 4; k++) {
        const int ol = ty * 4 + k;                  // local o in [0,32), warp-uniform
        const u64* wr  = w1s + (size_t)ol * (H_ * 8);
        const u64* w2r = w2s + (size_t)ol * H_;
        u64 accT0 = 0ull, accT1 = 0ull;             // sum y*w2*tanh(y)
        u64 accL0 = 0ull, accL1 = 0ull;             // sum y*w2

        #pragma unroll 4
        for (int h = 0; h < H_; h++) {
            const ulonglong2* r2 = (const ulonglong2*)(wr + h * 8);
            ulonglong2 qa = r2[0];                  // (w0,w0),(w1,w1)
            ulonglong2 qb = r2[1];                  // (w2,w2),(w3,w3)
            ulonglong2 qc = r2[2];                  // (w4,w4),(w5,w5)
            ulonglong2 qd = r2[3];                  // (w6,w6),(b1,b1)
            u64 w2p = w2r[h];

            u64 y0 = ffma2(fp[0][0], qa.x, qd.y);
            u64 y1 = ffma2(fp[1][0], qa.x, qd.y);
            y0 = ffma2(fp[0][1], qa.y, y0);
            y1 = ffma2(fp[1][1], qa.y, y1);
            y0 = ffma2(fp[0][2], qb.x, y0);
            y1 = ffma2(fp[1][2], qb.x, y1);
            y0 = ffma2(fp[0][3], qb.y, y0);
            y1 = ffma2(fp[1][3], qb.y, y1);
            y0 = ffma2(fp[0][4], qc.x, y0);
            y1 = ffma2(fp[1][4], qc.x, y1);
            y0 = ffma2(fp[0][5], qc.y, y0);
            y1 = ffma2(fp[1][5], qc.y, y1);
            y0 = ffma2(fp[0][6], qd.x, y0);
            y1 = ffma2(fp[1][6], qd.x, y1);

            u64 zw0 = fmul2(y0, w2p);
            u64 zw1 = fmul2(y1, w2p);

            float a0, a1, c0, c1;
            unpack2(y0, a0, a1);
            unpack2(y1, c0, c1);
            u64 t0 = pack2(tanh_ap(a0), tanh_ap(a1));
            u64 t1 = pack2(tanh_ap(c0), tanh_ap(c1));

            accT0 = ffma2(zw0, t0, accT0);
            accT1 = ffma2(zw1, t1, accT1);
            accL0 = fadd2(accL0, zw0);
            accL1 = fadd2(accL1, zw1);
        }

        u64 s0 = fadd2(accT0, accL0);
        u64 s1 = fadd2(accT1, accL1);
        float a0, a1, a2, a3;
        unpack2(s0, a0, a1);
        unpack2(s1, a2, a3);
        const float b2v = b2s[ol];
        float4 v; v.x = a0 + b2v; v.y = a1 + b2v; v.z = a2 + b2v; v.w = a3 + b2v;
        const int o = otile * 32 + ol;
        *(float4*)(g_partial + ((size_t)i * O_ + o) * B_ + b0) = v;   // coalesced
    }
}

// ---------------- reduce stage 1: sum 16-i chunks (1024 blocks) ----------------
__global__ void kan_reduce1() {
    int g = blockIdx.x * blockDim.x + threadIdx.x;     // [0, NCH*O_*B_) = 262144
    int c   = g >> 15;                                 // chunk 0..7
    int ob  = g & 32767;                               // (o,b) flat
    const float* p = g_partial + ((size_t)c * ICH) * (O_ * B_) + ob;
    float s0 = 0.f, s1 = 0.f, s2 = 0.f, s3 = 0.f;
    #pragma unroll
    for (int i = 0; i < ICH; i += 4) {
        s0 += p[(size_t)(i + 0) * (O_ * B_)];
        s1 += p[(size_t)(i + 1) * (O_ * B_)];
        s2 += p[(size_t)(i + 2) * (O_ * B_)];
        s3 += p[(size_t)(i + 3) * (O_ * B_)];
    }
    g_part2[(size_t)c * (O_ * B_) + ob] = (s0 + s1) + (s2 + s3);
}

// ---------------- reduce stage 2: sum 8 chunks, transpose to out[b][o] ----------------
__global__ void kan_reduce2(float* __restrict__ out) {
    int t = blockIdx.x * blockDim.x + threadIdx.x;     // [0, 32768)
    int b = t & (B_ - 1);
    int o = t >> 8;
    const float* p = g_part2 + (size_t)o * B_ + b;
    float s0 = 0.f, s1 = 0.f;
    #pragma unroll
    for (int c = 0; c < NCH; c += 2) {
        s0 += p[(size_t)(c + 0) * (O_ * B_)];
        s1 += p[(size_t)(c + 1) * (O_ * B_)];
    }
    out[(size_t)b * O_ + o] = s0 + s1;
}

// ---------------- launch ----------------
extern "C" void kernel_launch(void* const* d_in, const int* in_sizes, int n_in,
                              void* d_out, int out_size) {
    (void)in_sizes; (void)n_in; (void)out_size;
    const float* x  = (const float*)d_in[0];   // [256,128]
    const float* W1 = (const float*)d_in[1];   // [128,128,32,7]
    const float* W2 = (const float*)d_in[2];   // [128,128,1,32]
    const float* B1 = (const float*)d_in[3];   // [128,128,32]
    const float* B2 = (const float*)d_in[4];   // [128,128,1]
    float* out = (float*)d_out;                // [256,128]

    cudaFuncSetAttribute(kan_main, cudaFuncAttributeMaxDynamicSharedMemorySize, SMEM_BYTES);

    kan_main<<<dim3(8, I_), BD, SMEM_BYTES>>>(x, W1, W2, B1, B2);
    kan_reduce1<<<(NCH * O_ * B_) / BD, BD>>>();
    kan_reduce2<<<(O_ * B_) / BD, BD>>>(out);
}